// round 12
// baseline (speedup 1.0000x reference)
#include <cuda_runtime.h>

#define NN 10
#define MM 22
#define RR 2
#define NPAIR 55
#define TPB 256     // 8 warps = 2 groups x 4 warps; group covers 55 pairs x 2 halves in lanes
#define BPB 32      // batches per block; each group handles 16

typedef unsigned long long u64;

__device__ ulonglong2 gcoef[NPAIR][MM];   // packed (A_r0,A_r1 | B_r0,B_r1), alpha folded at m==0

__constant__ int PAIR_CELL[NPAIR] = {
  0,1,2,3,4,5,6,7,8,9,
  11,12,13,14,15,16,17,18,19,
  22,23,24,25,26,27,28,29,
  33,34,35,36,37,38,39,
  44,45,46,47,48,49,
  55,56,57,58,59,
  66,67,68,69,
  77,78,79,
  88,89,
  99};

__device__ __forceinline__ u64 pack2(float x, float y) {
    u64 r; asm("mov.b64 %0, {%1, %2};" : "=l"(r) : "f"(x), "f"(y)); return r;
}
__device__ __forceinline__ void unpack2(u64 v, float& x, float& y) {
    asm("mov.b64 {%0, %1}, %2;" : "=f"(x), "=f"(y) : "l"(v));
}
__device__ __forceinline__ u64 fma2(u64 a, u64 b, u64 c) {
    u64 d; asm("fma.rn.f32x2 %0, %1, %2, %3;" : "=l"(d) : "l"(a), "l"(b), "l"(c)); return d;
}
__device__ __forceinline__ u64 mul2(u64 a, u64 b) {
    u64 d; asm("mul.rn.f32x2 %0, %1, %2;" : "=l"(d) : "l"(a), "l"(b)); return d;
}
__device__ __forceinline__ u64 one2() { return 0x3f8000003f800000ULL; }

// ---- One-shot coefficient build: softmax over literal selectors + alpha fold ----
__global__ void tl_build(const float* __restrict__ sel, const float* __restrict__ alog) {
    int idx = blockIdx.x * blockDim.x + threadIdx.x;
    if (idx >= NPAIR * MM) return;
    int p = idx / MM, m = idx - p * MM;
    int i = 0, rem = p;
    while (rem >= NN - i) { rem -= NN - i; i++; }
    int j = i + rem;
    float Av[RR], Bv[RR];
#pragma unroll
    for (int r = 0; r < RR; r++) {
        const float* s = sel + (size_t)((((i * NN + j) * RR + r) * MM + m) * 3);
        float x0 = s[0] * 1.25f, x1 = s[1] * 1.25f, x2 = s[2] * 1.25f;  // /LIT_TEMP
        float mx = fmaxf(x0, fmaxf(x1, x2));
        float e0 = __expf(x0 - mx), e1 = __expf(x1 - mx), e2 = __expf(x2 - mx);
        float inv = 1.0f / (e0 + e1 + e2);
        float s0 = e0 * inv, s1 = e1 * inv, s2 = e2 * inv;
        float A = s0 + s2, Bc = s1 - s2;       // lit = A + B*u
        if (m == 0) {                           // fold alpha = sigmoid(alog)
            float a = alog[(i * NN + j) * RR + r];
            float alpha = 1.0f / (1.0f + __expf(-a));
            A *= alpha; Bc *= alpha;
        }
        Av[r] = A; Bv[r] = Bc;
    }
    ulonglong2 v;
    v.x = pack2(Av[0], Av[1]);
    v.y = pack2(Bv[0], Bv[1]);
    gcoef[p][m] = v;
}

// ---- Main kernel: pairs live in lanes, coefficients live in registers ----
__global__ void __launch_bounds__(TPB, 4)
tl_main(const float* __restrict__ pred,   // (B, M)
        float* __restrict__ out,          // (B, N, N)
        int B) {
    __shared__ ulonglong2 shc[MM][56];     // 19.7 KB transposed coef stage (row 56: bank spread)
    __shared__ u64   psm2[BPB][MM + 1];    // 5.9 KB pre-splatted (u,u) per (batch,m)
    __shared__ float wtile[BPB][101];      // 12.9 KB raw w tile (pad 101)
    __shared__ float rinvt[BPB][11];       // 1.4 KB per-(batch,row) 1/rowsum

    // Stage coefficients: src-linear coalesced LDG.128, transposed STS (one-time)
    {
        const ulonglong2* gsrc = &gcoef[0][0];
        for (int t = threadIdx.x; t < NPAIR * MM; t += TPB) {
            int p = t / MM, m = t - p * MM;
            shc[m][p] = gsrc[t];
        }
    }
    // Stage this block's 32x22 pred slab, coalesced; write packed (u,u) splats
    {
        const float* gp = pred + (size_t)blockIdx.x * BPB * MM;
        int nelem = BPB * MM;
        long gmax = (long)B * MM - (long)blockIdx.x * BPB * MM;
        if (nelem > gmax) nelem = (int)gmax;
        for (int t = threadIdx.x; t < nelem; t += TPB) {
            int bb = t / MM, m = t - bb * MM;
            float v = __ldg(gp + t);
            psm2[bb][m] = pack2(v, v);
        }
    }

    const int lane  = threadIdx.x & 31;
    const int w     = threadIdx.x >> 5;          // warp 0..7
    const int group = w >> 2;                    // 0 or 1
    const int gl    = ((w & 3) << 5) + lane;     // lane id within 4-warp group: 0..127
    const int pair  = gl >> 1;                   // 0..63 (55..63 inactive)
    const int half  = gl & 1;                    // which 11-m half
    const int pr    = pair < NPAIR ? pair : NPAIR - 1;   // clamp for safe loads
    const int m0    = half * 11;

    const bool writer = (half == 0) && (pair < NPAIR);
    const int  cell   = PAIR_CELL[pr];

    __syncthreads();

    // Lane's coefficients smem -> registers (one-time, near-conflict-free LDS.128)
    ulonglong2 cf[11];
#pragma unroll
    for (int k = 0; k < 11; k++) cf[k] = shc[m0 + k][pr];

    // ---- Phase 1: group loops over its 16 batches; lane computes its half-pair ----
    int bmax = B - blockIdx.x * BPB;
    if (bmax > BPB) bmax = BPB;
    int b0 = group * (BPB / 2);
    int b1 = b0 + (BPB / 2); if (b1 > bmax) b1 = bmax;

#pragma unroll 1
    for (int b = b0; b < b1; b++) {
        const u64* up = &psm2[b][m0];
        u64 accA = one2(), accB = one2();        // two chains for ILP
#pragma unroll
        for (int k = 0; k < 10; k += 2) {
            accA = mul2(accA, fma2(cf[k].y,     up[k],     cf[k].x));     // lit=B*u+A (both r)
            accB = mul2(accB, fma2(cf[k + 1].y, up[k + 1], cf[k + 1].x));
        }
        accA = mul2(accA, fma2(cf[10].y, up[10], cf[10].x));
        u64 mine = mul2(accA, accB);             // product over this lane's 11 m's
        u64 both = mul2(mine, __shfl_xor_sync(0xffffffffu, mine, 1));  // x partner half
        float c0f, c1f;
        unpack2(both, c0f, c1f);                 // c_r = alpha_r * clause_r
        float gg = c0f + c1f - c0f * c1f;        // 1 - (1-c0)(1-c1)
        float gc = fmaxf(gg, 1e-6f);
        if (writer) wtile[b][cell] = gc * gc;    // exp(log(g)/0.5) == g^2
    }
    __syncthreads();

    // ---- Phase 2: row sums -> 1/rowsum (320 (batch,row) cells, strided) ----
#pragma unroll 1
    for (int t = threadIdx.x; t < BPB * NN; t += TPB) {
        int bb = t & 31, row = t >> 5;
        const float* cells = &wtile[bb][row * NN];
        float s = 0.0f;
#pragma unroll 1
        for (int j = row; j < NN; j++) s += cells[j];
        rinvt[bb][row] = 1.0f / s;
    }
    __syncthreads();

    // ---- Phase 3: coalesced, normalized write-out with lower-triangle zeros ----
    int emax = bmax * (NN * NN);
    float* ob = out + (size_t)blockIdx.x * (BPB * NN * NN);
#pragma unroll 1
    for (int e = threadIdx.x; e < emax; e += TPB) {
        int bb  = e / 100, c = e - bb * 100;
        int row = c / 10,  col = c - row * 10;
        float v = (col >= row) ? wtile[bb][c] * rinvt[bb][row] : 0.0f;
        ob[e] = v;
    }
}

extern "C" void kernel_launch(void* const* d_in, const int* in_sizes, int n_in,
                              void* d_out, int out_size) {
    const float* pred = (const float*)d_in[0];   // (B, M)
    const float* sel  = (const float*)d_in[1];   // (N, N, R, M, 3)
    const float* alog = (const float*)d_in[2];   // (N, N, R)
    float* out = (float*)d_out;                  // (B, N, N)
    int B = in_sizes[0] / MM;
    tl_build<<<10, 128>>>(sel, alog);            // 1210 entries, one-shot
    int blocks = (B + BPB - 1) / BPB;            // 512 blocks, 4 blocks/SM, single wave
    tl_main<<<blocks, TPB>>>(pred, out, B);
}

// round 13
// speedup vs baseline: 1.1557x; 1.1557x over previous
#include <cuda_runtime.h>

#define NN 10
#define MM 22
#define RR 2
#define NPAIR 55
#define TPB 256     // 8 warps = 2 groups x 4 warps; group covers 55 pairs x 2 halves in lanes
#define BPB 32      // batches per block; each group handles 16

typedef unsigned long long u64;

__device__ ulonglong2 gcoef[NPAIR][MM];   // packed (A_r0,A_r1 | B_r0,B_r1), alpha folded at m==0

__constant__ int PAIR_CELL[NPAIR] = {
  0,1,2,3,4,5,6,7,8,9,
  11,12,13,14,15,16,17,18,19,
  22,23,24,25,26,27,28,29,
  33,34,35,36,37,38,39,
  44,45,46,47,48,49,
  55,56,57,58,59,
  66,67,68,69,
  77,78,79,
  88,89,
  99};

__device__ __forceinline__ u64 pack2(float x, float y) {
    u64 r; asm("mov.b64 %0, {%1, %2};" : "=l"(r) : "f"(x), "f"(y)); return r;
}
__device__ __forceinline__ void unpack2(u64 v, float& x, float& y) {
    asm("mov.b64 {%0, %1}, %2;" : "=f"(x), "=f"(y) : "l"(v));
}
__device__ __forceinline__ u64 fma2(u64 a, u64 b, u64 c) {
    u64 d; asm("fma.rn.f32x2 %0, %1, %2, %3;" : "=l"(d) : "l"(a), "l"(b), "l"(c)); return d;
}
__device__ __forceinline__ u64 mul2(u64 a, u64 b) {
    u64 d; asm("mul.rn.f32x2 %0, %1, %2;" : "=l"(d) : "l"(a), "l"(b)); return d;
}
__device__ __forceinline__ u64 one2() { return 0x3f8000003f800000ULL; }

// ---- One-shot coefficient build: softmax over literal selectors + alpha fold ----
__global__ void tl_build(const float* __restrict__ sel, const float* __restrict__ alog) {
    int idx = blockIdx.x * blockDim.x + threadIdx.x;
    if (idx >= NPAIR * MM) return;
    int p = idx / MM, m = idx - p * MM;
    int i = 0, rem = p;
    while (rem >= NN - i) { rem -= NN - i; i++; }
    int j = i + rem;
    float Av[RR], Bv[RR];
#pragma unroll
    for (int r = 0; r < RR; r++) {
        const float* s = sel + (size_t)((((i * NN + j) * RR + r) * MM + m) * 3);
        float x0 = s[0] * 1.25f, x1 = s[1] * 1.25f, x2 = s[2] * 1.25f;  // /LIT_TEMP
        float mx = fmaxf(x0, fmaxf(x1, x2));
        float e0 = __expf(x0 - mx), e1 = __expf(x1 - mx), e2 = __expf(x2 - mx);
        float inv = 1.0f / (e0 + e1 + e2);
        float s0 = e0 * inv, s1 = e1 * inv, s2 = e2 * inv;
        float A = s0 + s2, Bc = s1 - s2;       // lit = A + B*u
        if (m == 0) {                           // fold alpha = sigmoid(alog)
            float a = alog[(i * NN + j) * RR + r];
            float alpha = 1.0f / (1.0f + __expf(-a));
            A *= alpha; Bc *= alpha;
        }
        Av[r] = A; Bv[r] = Bc;
    }
    ulonglong2 v;
    v.x = pack2(Av[0], Av[1]);
    v.y = pack2(Bv[0], Bv[1]);
    gcoef[p][m] = v;
}

// ---- Main kernel: pairs live in lanes, coefficients live in registers ----
__global__ void __launch_bounds__(TPB, 4)
tl_main(const float* __restrict__ pred,   // (B, M)
        float* __restrict__ out,          // (B, N, N)
        int B) {
    __shared__ ulonglong2 shl[NPAIR * MM]; // 19.4 KB linear coef stage
    __shared__ u64   psm2[BPB][MM + 1];    // 5.9 KB pre-splatted (u,u) per (batch,m)
    __shared__ float wtile[BPB][101];      // 12.9 KB raw w tile (pad 101)
    __shared__ float rinvt[BPB][11];       // 1.4 KB per-(batch,row) 1/rowsum

    // Stage coefficients linearly: LDG.128 coalesced, STS.128 consecutive (no conflicts)
    {
        const ulonglong2* gsrc = &gcoef[0][0];
        for (int t = threadIdx.x; t < NPAIR * MM; t += TPB) shl[t] = gsrc[t];
    }
    // Stage this block's 32x22 pred slab, coalesced; write packed (u,u) splats
    {
        const float* gp = pred + (size_t)blockIdx.x * BPB * MM;
        int nelem = BPB * MM;
        long gmax = (long)B * MM - (long)blockIdx.x * BPB * MM;
        if (nelem > gmax) nelem = (int)gmax;
        for (int t = threadIdx.x; t < nelem; t += TPB) {
            int bb = t / MM, m = t - bb * MM;
            float v = __ldg(gp + t);
            psm2[bb][m] = pack2(v, v);
        }
    }

    const int lane  = threadIdx.x & 31;
    const int w     = threadIdx.x >> 5;          // warp 0..7
    const int group = w >> 2;                    // 0 or 1
    const int gl    = ((w & 3) << 5) + lane;     // lane id within 4-warp group: 0..127
    const int pair  = gl >> 1;                   // 0..63 (55..63 inactive)
    const int half  = gl & 1;                    // which 11-m half
    const int pr    = pair < NPAIR ? pair : NPAIR - 1;   // clamp for safe loads
    const int m0    = half * 11;

    const bool writer = (half == 0) && (pair < NPAIR);
    const int  cell   = PAIR_CELL[pr];

    __syncthreads();

    // Lane's coefficients smem -> registers.
    // Address = 176*gl + 16*k: lane stride 11 sixteen-byte units (ODD) -> each
    // 8-lane phase hits 8 distinct bank-quads -> conflict-free LDS.128.
    ulonglong2 cf[11];
#pragma unroll
    for (int k = 0; k < 11; k++) cf[k] = shl[pr * MM + m0 + k];

    // ---- Phase 1: group loops over its 16 batches; lane computes its half-pair ----
    int bmax = B - blockIdx.x * BPB;
    if (bmax > BPB) bmax = BPB;
    int b0 = group * (BPB / 2);
    int b1 = b0 + (BPB / 2); if (b1 > bmax) b1 = bmax;

#pragma unroll 1
    for (int b = b0; b < b1; b++) {
        const u64* up = &psm2[b][m0];
        u64 accA = one2(), accB = one2();        // two chains for ILP
#pragma unroll
        for (int k = 0; k < 10; k += 2) {
            accA = mul2(accA, fma2(cf[k].y,     up[k],     cf[k].x));     // lit=B*u+A (both r)
            accB = mul2(accB, fma2(cf[k + 1].y, up[k + 1], cf[k + 1].x));
        }
        accA = mul2(accA, fma2(cf[10].y, up[10], cf[10].x));
        u64 mine = mul2(accA, accB);             // product over this lane's 11 m's
        u64 both = mul2(mine, __shfl_xor_sync(0xffffffffu, mine, 1));  // x partner half
        float c0f, c1f;
        unpack2(both, c0f, c1f);                 // c_r = alpha_r * clause_r
        float gg = c0f + c1f - c0f * c1f;        // 1 - (1-c0)(1-c1)
        float gc = fmaxf(gg, 1e-6f);
        if (writer) wtile[b][cell] = gc * gc;    // exp(log(g)/0.5) == g^2
    }
    __syncthreads();

    // ---- Phase 2: row sums -> 1/rowsum (320 (batch,row) cells, strided) ----
#pragma unroll 1
    for (int t = threadIdx.x; t < BPB * NN; t += TPB) {
        int bb = t & 31, row = t >> 5;
        const float* cells = &wtile[bb][row * NN];
        float s = 0.0f;
#pragma unroll 1
        for (int j = row; j < NN; j++) s += cells[j];
        rinvt[bb][row] = 1.0f / s;
    }
    __syncthreads();

    // ---- Phase 3: coalesced, normalized write-out with lower-triangle zeros ----
    int emax = bmax * (NN * NN);
    float* ob = out + (size_t)blockIdx.x * (BPB * NN * NN);
#pragma unroll 1
    for (int e = threadIdx.x; e < emax; e += TPB) {
        int bb  = e / 100, c = e - bb * 100;
        int row = c / 10,  col = c - row * 10;
        float v = (col >= row) ? wtile[bb][c] * rinvt[bb][row] : 0.0f;
        ob[e] = v;
    }
}

extern "C" void kernel_launch(void* const* d_in, const int* in_sizes, int n_in,
                              void* d_out, int out_size) {
    const float* pred = (const float*)d_in[0];   // (B, M)
    const float* sel  = (const float*)d_in[1];   // (N, N, R, M, 3)
    const float* alog = (const float*)d_in[2];   // (N, N, R)
    float* out = (float*)d_out;                  // (B, N, N)
    int B = in_sizes[0] / MM;
    tl_build<<<10, 128>>>(sel, alog);            // 1210 entries, one-shot
    int blocks = (B + BPB - 1) / BPB;            // 512 blocks, 4 blocks/SM, single wave
    tl_main<<<blocks, TPB>>>(pred, out, B);
}